// round 8
// baseline (speedup 1.0000x reference)
#include <cuda_runtime.h>
#include <cuda_bf16.h>
#include <math.h>
#include <stdint.h>

static constexpr int Bc = 4;
static constexpr int Tc = 10;
static constexpr int Nc = 4096;
static constexpr int Hc = 32;
static constexpr int NHc = Nc * Hc;        // 131072
static constexpr int NCP = 136;            // out cols: 128 h + 4 x + 4 pad
static constexpr int NMB = Nc / 128;       // 32 m-blocks
static constexpr int NCHUNK = Nc / 64;     // 64 k-chunks of 64
static constexpr int KSPLIT = 4;
static constexpr int NITER = NCHUNK / KSPLIT;    // 16 chunks per CTA
static constexpr int A_TILE = 32768;       // 128x64 bf16 hi(16K)|lo(16K), SW128 rows
static constexpr int C_TILE = 34816;       // 136x64 bf16 hi(17408)|lo(17408), SW128
static constexpr int STAGE_B = A_TILE + C_TILE;  // 67584
static constexpr int NSTG = 3;
static constexpr int SMEM_DYN = NSTG * STAGE_B + 1024 + 64;

// ---- device scratch ----
__device__ __align__(128) unsigned char g_A[(size_t)Tc * NMB * NCHUNK * A_TILE];  // 671 MB
__device__ __align__(128) unsigned char g_C1[(size_t)Tc * NCHUNK * C_TILE];
__device__ __align__(128) unsigned char g_C2[(size_t)Tc * NCHUNK * C_TILE];
__device__ float g_Y[(size_t)KSPLIT * Tc * Nc * NCP];   // 89 MB
__device__ float g_RH[(size_t)Tc * Bc * Nc * Hc];
__device__ float g_g1fin[(size_t)Bc * Nc * 64];
__device__ float g_probe[32];

__device__ __forceinline__ float sigmoidf_(float x) { return 1.f / (1.f + expf(-x)); }

__device__ __forceinline__ void bsplit(float v, unsigned short& h, unsigned short& l) {
    __nv_bfloat16 hb = __float2bfloat16(v);
    h = __bfloat16_as_ushort(hb);
    l = __bfloat16_as_ushort(__float2bfloat16(v - __bfloat162float(hb)));
}

__device__ __forceinline__ uint32_t smem_u32(const void* p) {
    uint32_t a;
    asm("{ .reg .u64 t; cvta.to.shared.u64 t, %1; cvt.u32.u64 %0, t; }" : "=r"(a) : "l"(p));
    return a;
}

#define MBAR_INIT(m, n) asm volatile("mbarrier.init.shared.b64 [%0], %1;" :: "r"(m), "r"(n) : "memory")
#define MBAR_ARRIVE(m)  asm volatile("mbarrier.arrive.shared.b64 _, [%0];" :: "r"(m) : "memory")
#define MBAR_EXPECT_TX(m, b) \
    asm volatile("mbarrier.arrive.expect_tx.shared.b64 _, [%0], %1;" :: "r"(m), "r"(b) : "memory")

__device__ __forceinline__ void mbar_wait(uint32_t m, uint32_t parity) {
    asm volatile(
        "{\n\t.reg .pred P;\n\t"
        "WL_%=:\n\t"
        "mbarrier.try_wait.parity.acquire.cta.shared::cta.b64 P, [%0], %1, 0x989680;\n\t"
        "@P bra.uni WD_%=;\n\t"
        "bra.uni WL_%=;\n\t"
        "WD_%=:\n\t}"
        :: "r"(m), "r"(parity) : "memory");
}

__device__ __forceinline__ void bulk_g2s(uint32_t dst, const void* src, uint32_t bytes, uint32_t mbar) {
    asm volatile(
        "cp.async.bulk.shared::cluster.global.mbarrier::complete_tx::bytes [%0], [%1], %2, [%3];"
        :: "r"(dst), "l"(__cvta_generic_to_global(src)), "r"(bytes), "r"(mbar) : "memory");
}

__device__ __forceinline__ void mma16816(float* d, const unsigned* a, unsigned b0, unsigned b1) {
    asm volatile(
        "mma.sync.aligned.m16n8k16.row.col.f32.bf16.bf16.f32 "
        "{%0,%1,%2,%3}, {%4,%5,%6,%7}, {%8,%9}, {%0,%1,%2,%3};"
        : "+f"(d[0]), "+f"(d[1]), "+f"(d[2]), "+f"(d[3])
        : "r"(a[0]), "r"(a[1]), "r"(a[2]), "r"(a[3]), "r"(b0), "r"(b1));
}
__device__ __forceinline__ void ldsm4(unsigned* r, uint32_t addr) {
    asm volatile("ldmatrix.sync.aligned.m8n8.x4.shared.b16 {%0,%1,%2,%3}, [%4];"
                 : "=r"(r[0]), "=r"(r[1]), "=r"(r[2]), "=r"(r[3]) : "r"(addr));
}
__device__ __forceinline__ void ldsm2(unsigned* r, uint32_t addr) {
    asm volatile("ldmatrix.sync.aligned.m8n8.x2.shared.b16 {%0,%1}, [%2];"
                 : "=r"(r[0]), "=r"(r[1]) : "r"(addr));
}

// ---------------------------------------------------------------------------
// probe: no-op, shifts ncu capture window onto gemm1.
// ---------------------------------------------------------------------------
__global__ void probe_kernel() {
    if (threadIdx.x == 0) g_probe[0] = 1.f;
}

// ---------------------------------------------------------------------------
// prep: all 10 A_t, bf16 hi/lo, SW128-swizzled 128x64 tiles [t][mblk][chunk].
// ---------------------------------------------------------------------------
__global__ void prep_kernel(const float* __restrict__ dtw, const float* __restrict__ spec,
                            const float* __restrict__ lap, const float* __restrict__ td) {
    size_t base = ((size_t)blockIdx.x * 256 + threadIdx.x) * 8;
    int m = (int)(base >> 12), k0 = (int)(base & (Nc - 1));

    float sp[8], dw[8], lp[8], tv[8];
    *(float4*)(sp) = *(const float4*)(spec + base);
    *(float4*)(sp + 4) = *(const float4*)(spec + base + 4);
    *(float4*)(dw) = *(const float4*)(dtw + base);
    *(float4*)(dw + 4) = *(const float4*)(dtw + base + 4);
    *(float4*)(lp) = *(const float4*)(lap + base);
    *(float4*)(lp + 4) = *(const float4*)(lap + base + 4);
    *(float4*)(tv) = *(const float4*)(td + base);
    *(float4*)(tv + 4) = *(const float4*)(td + base + 4);

    unsigned short hA[8], lA[8], hB[8], lB[8], hC[8], lC[8], hD[8], lD[8];
    int thr[8];
#pragma unroll
    for (int j = 0; j < 8; j++) {
        float ab = 0.5f * (sp[j] + (m == k0 + j ? 1.f : 0.f));
        const float inv3 = 1.f / 3.f;
        bsplit(ab, hA[j], lA[j]);
        bsplit(ab + 0.5f * dw[j], hB[j], lB[j]);
        bsplit((2.f * ab + lp[j]) * inv3, hC[j], lC[j]);
        bsplit((2.f * ab + lp[j] + dw[j]) * inv3, hD[j], lD[j]);
        thr[j] = (dw[j] != 0.f) ? (int)((float)Tc - ceilf(fabsf(tv[j]))) : 1000000;
    }

    int mblk = m >> 7, row = m & 127, chunk = k0 >> 6;
    uint32_t off = (uint32_t)(row * 128 + (k0 & 63) * 2);
    uint32_t sw = off ^ ((off >> 3) & 0x70);

#pragma unroll
    for (int t = 0; t < Tc; t++) {
        __align__(16) unsigned short h8[8], l8[8];
        bool last = (t == Tc - 1);
#pragma unroll
        for (int j = 0; j < 8; j++) {
            bool s = t >= thr[j];
            h8[j] = last ? (s ? hD[j] : hC[j]) : (s ? hB[j] : hA[j]);
            l8[j] = last ? (s ? lD[j] : lC[j]) : (s ? lB[j] : lA[j]);
        }
        unsigned char* tile = g_A + ((size_t)((t * NMB + mblk) * NCHUNK + chunk)) * A_TILE;
        *(uint4*)(tile + sw) = *(const uint4*)h8;
        *(uint4*)(tile + 16384 + sw) = *(const uint4*)l8;
    }
}

// ---------------------------------------------------------------------------
// C tiles: 136 rows x 64 k bf16 hi/lo, SW128 rows. grid (chunk, t).
// ---------------------------------------------------------------------------
__global__ void buildC_kernel(const float* __restrict__ inputs, const float* __restrict__ states,
                              int phase) {
    int chunk = blockIdx.x, t = blockIdx.y;
    int tid = threadIdx.x;
    unsigned char* dst = (phase ? g_C2 : g_C1) + ((size_t)(t * NCHUNK + chunk)) * C_TILE;
    for (int p = tid; p < NCP * 32; p += 256) {
        int c = p >> 5, kp = p & 31;
        int n = chunk * 64 + kp * 2;
        float v0 = 0.f, v1 = 0.f;
        if (c < 128) {
            int b = c >> 5, k = c & 31;
            if (phase == 0) {
                size_t i0 = (((size_t)(t * Bc + b)) << 17) + (size_t)n * Hc + k;
                v0 = states[i0];
                v1 = states[i0 + Hc];
            } else {
                size_t i0 = (((size_t)(t * Bc + b)) * Nc + n) * Hc + k;
                v0 = g_RH[i0];
                v1 = g_RH[i0 + Hc];
            }
        } else if (c < 132) {
            int b = c - 128;
            size_t i0 = ((size_t)b * Tc + t) * Nc + n;
            v0 = inputs[i0];
            v1 = inputs[i0 + 1];
        }
        unsigned short h0, l0, h1, l1;
        bsplit(v0, h0, l0);
        bsplit(v1, h1, l1);
        uint32_t off = (uint32_t)(c * 128 + kp * 4);
        uint32_t sw = off ^ ((off >> 3) & 0x70);
        *(uint32_t*)(dst + sw) = (uint32_t)h0 | ((uint32_t)h1 << 16);
        *(uint32_t*)(dst + 17408 + sw) = (uint32_t)l0 | ((uint32_t)l1 << 16);
    }
}

// ---------------------------------------------------------------------------
// GEMM: bulk-copy 3-stage ring -> ldmatrix -> bf16 split-3 mma.sync.
// Warp tiling 2(m) x 4(n): warp = wm*4+wn? (wm = warp>>2).
// grid (32 mblk, 10 t, KSPLIT), 256 threads.
// ---------------------------------------------------------------------------
__global__ void __launch_bounds__(256, 1) gemm_kernel(int phase) {
    extern __shared__ unsigned char dsm[];
    uint32_t raw = smem_u32(dsm);
    uint32_t sbase = (raw + 1023) & ~1023u;
    uint32_t fullm = sbase + NSTG * STAGE_B;
    uint32_t emptym = fullm + NSTG * 8;

    const int tid = threadIdx.x;
    const int warp = tid >> 5, lane = tid & 31;
    const int mblk = blockIdx.x, t = blockIdx.y, z = blockIdx.z;
    const int wm = warp >> 2, wn = warp & 3;
    const int g = lane >> 2, tg = lane & 3;

    if (tid == 0) {
        for (int s = 0; s < NSTG; s++) {
            MBAR_INIT(fullm + 8 * s, 1);
            MBAR_INIT(emptym + 8 * s, 256);
        }
        asm volatile("fence.proxy.async.shared::cta;" ::: "memory");
    }
    __syncthreads();

    const unsigned char* Asrc =
        g_A + ((size_t)((t * NMB + mblk) * NCHUNK + z * NITER)) * A_TILE;
    const unsigned char* Csrc =
        (phase ? g_C2 : g_C1) + ((size_t)(t * NCHUNK + z * NITER)) * C_TILE;

    if (tid == 0) {
#pragma unroll
        for (int s = 0; s < NSTG; s++) {
            uint32_t st = sbase + s * STAGE_B;
            MBAR_EXPECT_TX(fullm + 8 * s, STAGE_B);
            bulk_g2s(st, Asrc + (size_t)s * A_TILE, A_TILE, fullm + 8 * s);
            bulk_g2s(st + A_TILE, Csrc + (size_t)s * C_TILE, C_TILE, fullm + 8 * s);
        }
    }

    // A fragment bases: 4 m-frags at rows wm*64 + f*16
    uint32_t baseAf[4], xAf[4];
#pragma unroll
    for (int f = 0; f < 4; f++) {
        int rowA = wm * 64 + f * 16 + (lane & 15);
        baseAf[f] = (uint32_t)rowA * 128;
        xAf[f] = (uint32_t)(rowA & 7) * 16;
    }
    const uint32_t subA = (uint32_t)(lane >> 4) * 16;

    // B pairs: J = 2*wn + p covers tiles 2J, 2J+1 (tiles 4wn..4wn+3)
    uint32_t baseBp[2], xBp[2];
#pragma unroll
    for (int p = 0; p < 2; p++) {
        int J = 2 * wn + p;
        int rowB = (2 * J + (lane >> 4)) * 8 + (lane & 7);
        baseBp[p] = (uint32_t)rowB * 128;
        xBp[p] = (uint32_t)(rowB & 7) * 16;
    }
    // x/pad tile 16 (handled by wn==0): ldsm2 uses lanes 0-15
    int rowX = 128 + (lane & 7) + ((lane >> 3) & 1) * 0;  // rows 128..135
    uint32_t baseX = (uint32_t)(128 + (lane & 7)) * 128;
    uint32_t xX = (uint32_t)((128 + (lane & 7)) & 7) * 16;
    (void)rowX;
    const uint32_t subB = (uint32_t)((lane >> 3) & 1) * 16;

    float acc[2][2][4][4];   // [pair][tileInPair][mfrag][4]
#pragma unroll
    for (int p = 0; p < 2; p++)
#pragma unroll
        for (int ti = 0; ti < 2; ti++)
#pragma unroll
            for (int f = 0; f < 4; f++)
#pragma unroll
                for (int q = 0; q < 4; q++) acc[p][ti][f][q] = 0.f;
    float accx[4][4];
#pragma unroll
    for (int f = 0; f < 4; f++)
#pragma unroll
        for (int q = 0; q < 4; q++) accx[f][q] = 0.f;

    for (int i = 0; i < NITER; i++) {
        const int s = i % NSTG;
        const uint32_t ph = (uint32_t)((i / NSTG) & 1);
        mbar_wait(fullm + 8 * s, ph);

        const uint32_t stA = sbase + s * STAGE_B;
        const uint32_t stC = stA + A_TILE;
#pragma unroll
        for (int ks = 0; ks < 4; ++ks) {
            const uint32_t colA = (uint32_t)ks * 32 + subA;
            unsigned ah[4][4], al[4][4];
#pragma unroll
            for (int f = 0; f < 4; f++) {
                ldsm4(ah[f], stA + baseAf[f] + (colA ^ xAf[f]));
                ldsm4(al[f], stA + 16384 + baseAf[f] + (colA ^ xAf[f]));
            }
            const uint32_t colB = (uint32_t)ks * 32 + subB;
#pragma unroll
            for (int p = 0; p < 2; ++p) {
                unsigned bh[4], bl[4];
                uint32_t ob = baseBp[p] + (colB ^ xBp[p]);
                ldsm4(bh, stC + ob);
                ldsm4(bl, stC + 17408 + ob);
#pragma unroll
                for (int f = 0; f < 4; f++) {
                    mma16816(acc[p][0][f], ah[f], bh[0], bh[1]);
                    mma16816(acc[p][0][f], ah[f], bl[0], bl[1]);
                    mma16816(acc[p][0][f], al[f], bh[0], bh[1]);
                    mma16816(acc[p][1][f], ah[f], bh[2], bh[3]);
                    mma16816(acc[p][1][f], ah[f], bl[2], bl[3]);
                    mma16816(acc[p][1][f], al[f], bh[2], bh[3]);
                }
            }
            if (wn == 0) {
                unsigned bh2[2], bl2[2];
                uint32_t ob = baseX + (colB ^ xX);
                ldsm2(bh2, stC + ob);
                ldsm2(bl2, stC + 17408 + ob);
#pragma unroll
                for (int f = 0; f < 4; f++) {
                    mma16816(accx[f], ah[f], bh2[0], bh2[1]);
                    mma16816(accx[f], ah[f], bl2[0], bl2[1]);
                    mma16816(accx[f], al[f], bh2[0], bh2[1]);
                }
            }
        }
        MBAR_ARRIVE(emptym + 8 * s);
        if (tid == 0 && i + NSTG < NITER) {
            mbar_wait(emptym + 8 * s, ph);
            uint32_t st = sbase + s * STAGE_B;
            MBAR_EXPECT_TX(fullm + 8 * s, STAGE_B);
            bulk_g2s(st, Asrc + (size_t)(i + NSTG) * A_TILE, A_TILE, fullm + 8 * s);
            bulk_g2s(st + A_TILE, Csrc + (size_t)(i + NSTG) * C_TILE, C_TILE, fullm + 8 * s);
        }
    }

    float* Yt = g_Y + ((size_t)(z * Tc + t) * Nc + mblk * 128) * NCP;
#pragma unroll
    for (int p = 0; p < 2; ++p)
#pragma unroll
        for (int ti = 0; ti < 2; ++ti) {
            int col = (4 * wn + 2 * p + ti) * 8 + tg * 2;
#pragma unroll
            for (int f = 0; f < 4; ++f) {
                int r0 = wm * 64 + f * 16 + g;
                *(float2*)(Yt + (size_t)r0 * NCP + col) =
                    make_float2(acc[p][ti][f][0], acc[p][ti][f][1]);
                *(float2*)(Yt + (size_t)(r0 + 8) * NCP + col) =
                    make_float2(acc[p][ti][f][2], acc[p][ti][f][3]);
            }
        }
    if (wn == 0) {
        int col = 128 + tg * 2;
#pragma unroll
        for (int f = 0; f < 4; ++f) {
            int r0 = wm * 64 + f * 16 + g;
            *(float2*)(Yt + (size_t)r0 * NCP + col) = make_float2(accx[f][0], accx[f][1]);
            *(float2*)(Yt + (size_t)(r0 + 8) * NCP + col) = make_float2(accx[f][2], accx[f][3]);
        }
    }
}

// ---------------------------------------------------------------------------
__global__ void gate_kernel(const float* __restrict__ W1, const float* __restrict__ b1,
                            const float* __restrict__ states) {
    __shared__ float W1s[33 * 64];
    __shared__ float b1s[64];
    int tid = threadIdx.x;
    for (int i = tid; i < 33 * 64; i += 256) W1s[i] = W1[i];
    if (tid < 64) b1s[tid] = b1[tid];
    __syncthreads();

    int w = blockIdx.x * 8 + (tid >> 5);
    int lane = tid & 31;
    int b = w >> 12, m = w & (Nc - 1);

    float acc0 = 0.f, acc1 = 0.f;
    for (int t = 0; t < Tc; t++) {
        float ys = 0.f, yx = 0.f;
#pragma unroll
        for (int s = 0; s < KSPLIT; s++) {
            const float* yp = g_Y + ((size_t)(s * Tc + t) * Nc + m) * NCP;
            ys += yp[b * Hc + lane];
            yx += yp[128 + b];
        }
        acc0 += yx * W1s[lane] + b1s[lane];
        acc1 += yx * W1s[lane + 32] + b1s[lane + 32];
#pragma unroll
        for (int j = 0; j < 32; j++) {
            float yj = __shfl_sync(0xffffffffu, ys, j);
            acc0 += yj * W1s[(j + 1) * 64 + lane];
            acc1 += yj * W1s[(j + 1) * 64 + lane + 32];
        }
        if (m < Nc / 2) {
            float r0 = sigmoidf_(acc0);
            float r1 = sigmoidf_(acc1);
            int n0 = 2 * m;
            size_t hidx = ((size_t)t * Bc + b) * NHc + (size_t)n0 * Hc + lane;
            size_t ridx = (((size_t)t * Bc + b) * Nc + n0) * Hc + lane;
            g_RH[ridx] = r0 * states[hidx];
            g_RH[ridx + Hc] = r1 * states[hidx + Hc];
        }
    }
    size_t o = ((size_t)b * Nc + m) * 64;
    g_g1fin[o + lane] = acc0;
    g_g1fin[o + 32 + lane] = acc1;
}

__global__ void final_kernel(const float* __restrict__ W2, const float* __restrict__ b2,
                             const float* __restrict__ states, float* __restrict__ out) {
    __shared__ float W2s[33 * 32];
    __shared__ float b2s[32];
    int tid = threadIdx.x;
    for (int i = tid; i < 33 * 32; i += 256) W2s[i] = W2[i];
    if (tid < 32) b2s[tid] = b2[tid];
    __syncthreads();

    int w = blockIdx.x * 8 + (tid >> 5);
    int lane = tid & 31;
    int b = w >> 12, n = w & (Nc - 1);

    float ys = 0.f, yx = 0.f;
    for (int t = 0; t < Tc; t++) {
#pragma unroll
        for (int s = 0; s < KSPLIT; s++) {
            const float* yp = g_Y + ((size_t)(s * Tc + t) * Nc + n) * NCP;
            ys += yp[b * Hc + lane];
            yx += yp[128 + b];
        }
    }
    float acc = yx * W2s[lane] + (float)Tc * b2s[lane];
#pragma unroll
    for (int j = 0; j < 32; j++) {
        float yj = __shfl_sync(0xffffffffu, ys, j);
        acc += yj * W2s[(j + 1) * 32 + lane];
    }
    float cc = tanhf(acc);
    float g1 = g_g1fin[((size_t)b * Nc + (Nc / 2) + (n >> 1)) * 64 + (n & 1) * 32 + lane];
    float u = sigmoidf_(g1);
    float h = states[((size_t)(Tc - 1) * Bc + b) * NHc + (size_t)n * Hc + lane];
    out[(size_t)b * NHc + (size_t)n * Hc + lane] = u * h + (1.f - u) * cc;
}

// ---------------------------------------------------------------------------
extern "C" void kernel_launch(void* const* d_in, const int* in_sizes, int n_in,
                              void* d_out, int out_size) {
    const float* inputs = (const float*)d_in[0];
    const float* states = (const float*)d_in[1];
    const float* dtw    = (const float*)d_in[2];
    const float* spec   = (const float*)d_in[3];
    const float* lap    = (const float*)d_in[4];
    const float* td     = (const float*)d_in[5];
    const float* W1     = (const float*)d_in[6];
    const float* b1     = (const float*)d_in[7];
    const float* W2     = (const float*)d_in[8];
    const float* b2     = (const float*)d_in[9];
    float* out = (float*)d_out;

    cudaFuncSetAttribute(gemm_kernel, cudaFuncAttributeMaxDynamicSharedMemorySize, SMEM_DYN);

    probe_kernel<<<1, 32>>>();   // shifts ncu -s window onto gemm1
    prep_kernel<<<(int)((size_t)Nc * Nc / 8 / 256), 256>>>(dtw, spec, lap, td);
    buildC_kernel<<<dim3(NCHUNK, Tc), 256>>>(inputs, states, 0);
    gemm_kernel<<<dim3(NMB, Tc, KSPLIT), 256, SMEM_DYN>>>(0);
    gate_kernel<<<(Bc * Nc) / 8, 256>>>(W1, b1, states);
    buildC_kernel<<<dim3(NCHUNK, Tc), 256>>>(inputs, states, 1);
    gemm_kernel<<<dim3(NMB, Tc, KSPLIT), 256, SMEM_DYN>>>(1);
    final_kernel<<<(Bc * Nc) / 8, 256>>>(W2, b2, states, out);
}

// round 9
// speedup vs baseline: 1.1189x; 1.1189x over previous
#include <cuda_runtime.h>
#include <cuda_bf16.h>
#include <math.h>
#include <stdint.h>

static constexpr int Bc = 4;
static constexpr int Tc = 10;
static constexpr int Nc = 4096;
static constexpr int Hc = 32;
static constexpr int NHc = Nc * Hc;        // 131072
static constexpr int NCP = 136;            // out cols: 128 h + 4 x + 4 pad
static constexpr int NT = NCP / 8;         // 17 n-tiles per warp
static constexpr int NMB = Nc / 128;       // 32 m-blocks
static constexpr int KC = 32;              // k per chunk
static constexpr int NCHUNK = Nc / KC;     // 128
static constexpr int KSPLIT = 4;
static constexpr int NITER = NCHUNK / KSPLIT;    // 32 chunks per CTA
static constexpr int A_TILE = 16384;       // 128x32 bf16 hi(8192)|lo(8192), 64B rows (SW64)
static constexpr int C_TILE = 17408;       // 136x32 bf16 hi(8704)|lo(8704), 64B rows
static constexpr int STAGE_B = A_TILE + C_TILE;  // 33792
static constexpr int NSTG = 3;
static constexpr int SMEM_DYN = NSTG * STAGE_B + 1024 + 64;  // ~102.5 KB -> 2 CTAs/SM

// SW64 swizzle for 64-byte rows: o ^ ((o>>3)&0x30)
__host__ __device__ __forceinline__ uint32_t sw64(uint32_t o) { return o ^ ((o >> 3) & 0x30); }

// ---- device scratch ----
__device__ __align__(128) unsigned char g_A[(size_t)Tc * NMB * NCHUNK * A_TILE];  // 671 MB
__device__ __align__(128) unsigned char g_C1[(size_t)Tc * NCHUNK * C_TILE];
__device__ __align__(128) unsigned char g_C2[(size_t)Tc * NCHUNK * C_TILE];
__device__ float g_Y[(size_t)KSPLIT * Tc * Nc * NCP];   // 89 MB
__device__ float g_RH[(size_t)Tc * Bc * Nc * Hc];
__device__ float g_g1fin[(size_t)Bc * Nc * 64];
__device__ float g_probe[32];

__device__ __forceinline__ float sigmoidf_(float x) { return 1.f / (1.f + expf(-x)); }

__device__ __forceinline__ void bsplit(float v, unsigned short& h, unsigned short& l) {
    __nv_bfloat16 hb = __float2bfloat16(v);
    h = __bfloat16_as_ushort(hb);
    l = __bfloat16_as_ushort(__float2bfloat16(v - __bfloat162float(hb)));
}

__device__ __forceinline__ uint32_t smem_u32(const void* p) {
    uint32_t a;
    asm("{ .reg .u64 t; cvta.to.shared.u64 t, %1; cvt.u32.u64 %0, t; }" : "=r"(a) : "l"(p));
    return a;
}

#define MBAR_INIT(m, n) asm volatile("mbarrier.init.shared.b64 [%0], %1;" :: "r"(m), "r"(n) : "memory")
#define MBAR_ARRIVE(m)  asm volatile("mbarrier.arrive.shared.b64 _, [%0];" :: "r"(m) : "memory")
#define MBAR_EXPECT_TX(m, b) \
    asm volatile("mbarrier.arrive.expect_tx.shared.b64 _, [%0], %1;" :: "r"(m), "r"(b) : "memory")

__device__ __forceinline__ void mbar_wait(uint32_t m, uint32_t parity) {
    asm volatile(
        "{\n\t.reg .pred P;\n\t"
        "WL_%=:\n\t"
        "mbarrier.try_wait.parity.acquire.cta.shared::cta.b64 P, [%0], %1, 0x989680;\n\t"
        "@P bra.uni WD_%=;\n\t"
        "bra.uni WL_%=;\n\t"
        "WD_%=:\n\t}"
        :: "r"(m), "r"(parity) : "memory");
}

__device__ __forceinline__ void bulk_g2s(uint32_t dst, const void* src, uint32_t bytes, uint32_t mbar) {
    asm volatile(
        "cp.async.bulk.shared::cluster.global.mbarrier::complete_tx::bytes [%0], [%1], %2, [%3];"
        :: "r"(dst), "l"(__cvta_generic_to_global(src)), "r"(bytes), "r"(mbar) : "memory");
}

__device__ __forceinline__ void mma16816(float* d, const unsigned* a, unsigned b0, unsigned b1) {
    asm volatile(
        "mma.sync.aligned.m16n8k16.row.col.f32.bf16.bf16.f32 "
        "{%0,%1,%2,%3}, {%4,%5,%6,%7}, {%8,%9}, {%0,%1,%2,%3};"
        : "+f"(d[0]), "+f"(d[1]), "+f"(d[2]), "+f"(d[3])
        : "r"(a[0]), "r"(a[1]), "r"(a[2]), "r"(a[3]), "r"(b0), "r"(b1));
}
__device__ __forceinline__ void ldsm4(unsigned* r, uint32_t addr) {
    asm volatile("ldmatrix.sync.aligned.m8n8.x4.shared.b16 {%0,%1,%2,%3}, [%4];"
                 : "=r"(r[0]), "=r"(r[1]), "=r"(r[2]), "=r"(r[3]) : "r"(addr));
}
__device__ __forceinline__ void ldsm2(unsigned* r, uint32_t addr) {
    asm volatile("ldmatrix.sync.aligned.m8n8.x2.shared.b16 {%0,%1}, [%2];"
                 : "=r"(r[0]), "=r"(r[1]) : "r"(addr));
}

// ---------------------------------------------------------------------------
__global__ void probe_kernel() {
    if (threadIdx.x == 0) g_probe[0] = 1.f;
}

// ---------------------------------------------------------------------------
// prep: all 10 A_t, bf16 hi/lo, SW64-swizzled 128x32 tiles [t][mblk][chunk].
// ---------------------------------------------------------------------------
__global__ void prep_kernel(const float* __restrict__ dtw, const float* __restrict__ spec,
                            const float* __restrict__ lap, const float* __restrict__ td) {
    size_t base = ((size_t)blockIdx.x * 256 + threadIdx.x) * 8;
    int m = (int)(base >> 12), k0 = (int)(base & (Nc - 1));

    float sp[8], dw[8], lp[8], tv[8];
    *(float4*)(sp) = *(const float4*)(spec + base);
    *(float4*)(sp + 4) = *(const float4*)(spec + base + 4);
    *(float4*)(dw) = *(const float4*)(dtw + base);
    *(float4*)(dw + 4) = *(const float4*)(dtw + base + 4);
    *(float4*)(lp) = *(const float4*)(lap + base);
    *(float4*)(lp + 4) = *(const float4*)(lap + base + 4);
    *(float4*)(tv) = *(const float4*)(td + base);
    *(float4*)(tv + 4) = *(const float4*)(td + base + 4);

    unsigned short hA[8], lA[8], hB[8], lB[8], hC[8], lC[8], hD[8], lD[8];
    int thr[8];
#pragma unroll
    for (int j = 0; j < 8; j++) {
        float ab = 0.5f * (sp[j] + (m == k0 + j ? 1.f : 0.f));
        const float inv3 = 1.f / 3.f;
        bsplit(ab, hA[j], lA[j]);
        bsplit(ab + 0.5f * dw[j], hB[j], lB[j]);
        bsplit((2.f * ab + lp[j]) * inv3, hC[j], lC[j]);
        bsplit((2.f * ab + lp[j] + dw[j]) * inv3, hD[j], lD[j]);
        thr[j] = (dw[j] != 0.f) ? (int)((float)Tc - ceilf(fabsf(tv[j]))) : 1000000;
    }

    int mblk = m >> 7, row = m & 127, chunk = k0 >> 5;
    uint32_t sw = sw64((uint32_t)(row * 64 + (k0 & 31) * 2));

#pragma unroll
    for (int t = 0; t < Tc; t++) {
        __align__(16) unsigned short h8[8], l8[8];
        bool last = (t == Tc - 1);
#pragma unroll
        for (int j = 0; j < 8; j++) {
            bool s = t >= thr[j];
            h8[j] = last ? (s ? hD[j] : hC[j]) : (s ? hB[j] : hA[j]);
            l8[j] = last ? (s ? lD[j] : lC[j]) : (s ? lB[j] : lA[j]);
        }
        unsigned char* tile = g_A + ((size_t)((t * NMB + mblk) * NCHUNK + chunk)) * A_TILE;
        *(uint4*)(tile + sw) = *(const uint4*)h8;
        *(uint4*)(tile + 8192 + sw) = *(const uint4*)l8;
    }
}

// ---------------------------------------------------------------------------
// C tiles: 136 rows x 32 k bf16 hi/lo, 64B rows SW64. grid (chunk, t).
// ---------------------------------------------------------------------------
__global__ void buildC_kernel(const float* __restrict__ inputs, const float* __restrict__ states,
                              int phase) {
    int chunk = blockIdx.x, t = blockIdx.y;
    int tid = threadIdx.x;
    unsigned char* dst = (phase ? g_C2 : g_C1) + ((size_t)(t * NCHUNK + chunk)) * C_TILE;
    for (int p = tid; p < NCP * 16; p += 256) {
        int c = p >> 4, kp = p & 15;
        int n = chunk * KC + kp * 2;
        float v0 = 0.f, v1 = 0.f;
        if (c < 128) {
            int b = c >> 5, k = c & 31;
            if (phase == 0) {
                size_t i0 = (((size_t)(t * Bc + b)) << 17) + (size_t)n * Hc + k;
                v0 = states[i0];
                v1 = states[i0 + Hc];
            } else {
                size_t i0 = (((size_t)(t * Bc + b)) * Nc + n) * Hc + k;
                v0 = g_RH[i0];
                v1 = g_RH[i0 + Hc];
            }
        } else if (c < 132) {
            int b = c - 128;
            size_t i0 = ((size_t)b * Tc + t) * Nc + n;
            v0 = inputs[i0];
            v1 = inputs[i0 + 1];
        }
        unsigned short h0, l0, h1, l1;
        bsplit(v0, h0, l0);
        bsplit(v1, h1, l1);
        uint32_t sw = sw64((uint32_t)(c * 64 + kp * 4));
        *(uint32_t*)(dst + sw) = (uint32_t)h0 | ((uint32_t)h1 << 16);
        *(uint32_t*)(dst + 8704 + sw) = (uint32_t)l0 | ((uint32_t)l1 << 16);
    }
}

// ---------------------------------------------------------------------------
// GEMM: bulk-copy 3-stage ring -> ldmatrix -> bf16 split-3 mma.sync.
// Warp owns 16 M-rows x all 17 n-tiles (R7 tiling). 2 CTAs/SM.
// grid (32 mblk, 10 t, KSPLIT), 256 threads.
// ---------------------------------------------------------------------------
__global__ void __launch_bounds__(256, 2) gemm_kernel(int phase) {
    extern __shared__ unsigned char dsm[];
    uint32_t raw = smem_u32(dsm);
    uint32_t sbase = (raw + 1023) & ~1023u;
    uint32_t fullm = sbase + NSTG * STAGE_B;
    uint32_t emptym = fullm + NSTG * 8;

    const int tid = threadIdx.x;
    const int warp = tid >> 5, lane = tid & 31;
    const int mblk = blockIdx.x, t = blockIdx.y, z = blockIdx.z;
    const int mr = warp * 16;
    const int g = lane >> 2, tg = lane & 3;

    if (tid == 0) {
        for (int s = 0; s < NSTG; s++) {
            MBAR_INIT(fullm + 8 * s, 1);
            MBAR_INIT(emptym + 8 * s, 256);
        }
        asm volatile("fence.proxy.async.shared::cta;" ::: "memory");
    }
    __syncthreads();

    const unsigned char* Asrc =
        g_A + ((size_t)((t * NMB + mblk) * NCHUNK + z * NITER)) * A_TILE;
    const unsigned char* Csrc =
        (phase ? g_C2 : g_C1) + ((size_t)(t * NCHUNK + z * NITER)) * C_TILE;

    if (tid == 0) {
#pragma unroll
        for (int s = 0; s < NSTG; s++) {
            uint32_t st = sbase + s * STAGE_B;
            MBAR_EXPECT_TX(fullm + 8 * s, STAGE_B);
            bulk_g2s(st, Asrc + (size_t)s * A_TILE, A_TILE, fullm + 8 * s);
            bulk_g2s(st + A_TILE, Csrc + (size_t)s * C_TILE, C_TILE, fullm + 8 * s);
        }
    }

    // per-lane ldmatrix bases; swizzle XOR constant per row ((row>>1)&3)<<4
    const int rowA = mr + (lane & 15);
    const uint32_t baseA = (uint32_t)rowA * 64;
    const uint32_t xA = (uint32_t)((rowA >> 1) & 3) << 4;
    const uint32_t subA = (uint32_t)(lane >> 4) * 16;
    uint32_t baseB[9], xB[9];
#pragma unroll
    for (int j = 0; j < 9; j++) {
        int rowB = (2 * j + (lane >> 4)) * 8 + (lane & 7);
        if (j == 8) rowB = 128 + (lane & 7);
        baseB[j] = (uint32_t)rowB * 64;
        xB[j] = (uint32_t)((rowB >> 1) & 3) << 4;
    }
    const uint32_t subB = (uint32_t)((lane >> 3) & 1) * 16;

    float acc[NT][4];
#pragma unroll
    for (int i = 0; i < NT; i++)
#pragma unroll
        for (int j = 0; j < 4; j++) acc[i][j] = 0.f;

    for (int i = 0; i < NITER; i++) {
        const int s = i % NSTG;
        const uint32_t ph = (uint32_t)((i / NSTG) & 1);
        mbar_wait(fullm + 8 * s, ph);

        const uint32_t stA = sbase + s * STAGE_B;
        const uint32_t stC = stA + A_TILE;
#pragma unroll
        for (int ks = 0; ks < 2; ++ks) {
            const uint32_t colA = (uint32_t)ks * 32 + subA;
            unsigned ah[4], al[4];
            ldsm4(ah, stA + baseA + (colA ^ xA));
            ldsm4(al, stA + 8192 + baseA + (colA ^ xA));
            const uint32_t colB = (uint32_t)ks * 32 + subB;
#pragma unroll
            for (int j = 0; j < 8; ++j) {
                unsigned bh[4], bl[4];
                uint32_t ob = baseB[j] + (colB ^ xB[j]);
                ldsm4(bh, stC + ob);
                ldsm4(bl, stC + 8704 + ob);
                mma16816(acc[2 * j], ah, bh[0], bh[1]);
                mma16816(acc[2 * j], ah, bl[0], bl[1]);
                mma16816(acc[2 * j], al, bh[0], bh[1]);
                mma16816(acc[2 * j + 1], ah, bh[2], bh[3]);
                mma16816(acc[2 * j + 1], ah, bl[2], bl[3]);
                mma16816(acc[2 * j + 1], al, bh[2], bh[3]);
            }
            {
                unsigned bh2[2], bl2[2];
                uint32_t ob = baseB[8] + (colB ^ xB[8]);
                ldsm2(bh2, stC + ob);
                ldsm2(bl2, stC + 8704 + ob);
                mma16816(acc[16], ah, bh2[0], bh2[1]);
                mma16816(acc[16], ah, bl2[0], bl2[1]);
                mma16816(acc[16], al, bh2[0], bh2[1]);
            }
        }
        MBAR_ARRIVE(emptym + 8 * s);
        if (tid == 0 && i + NSTG < NITER) {
            mbar_wait(emptym + 8 * s, ph);
            uint32_t st = sbase + s * STAGE_B;
            MBAR_EXPECT_TX(fullm + 8 * s, STAGE_B);
            bulk_g2s(st, Asrc + (size_t)(i + NSTG) * A_TILE, A_TILE, fullm + 8 * s);
            bulk_g2s(st + A_TILE, Csrc + (size_t)(i + NSTG) * C_TILE, C_TILE, fullm + 8 * s);
        }
    }

    float* Yt = g_Y + ((size_t)(z * Tc + t) * Nc + mblk * 128) * NCP;
#pragma unroll
    for (int nt = 0; nt < NT; ++nt) {
        int col = nt * 8 + tg * 2;
        *(float2*)(Yt + (size_t)(mr + g) * NCP + col) = make_float2(acc[nt][0], acc[nt][1]);
        *(float2*)(Yt + (size_t)(mr + g + 8) * NCP + col) = make_float2(acc[nt][2], acc[nt][3]);
    }
}

// ---------------------------------------------------------------------------
__global__ void gate_kernel(const float* __restrict__ W1, const float* __restrict__ b1,
                            const float* __restrict__ states) {
    __shared__ float W1s[33 * 64];
    __shared__ float b1s[64];
    int tid = threadIdx.x;
    for (int i = tid; i < 33 * 64; i += 256) W1s[i] = W1[i];
    if (tid < 64) b1s[tid] = b1[tid];
    __syncthreads();

    int w = blockIdx.x * 8 + (tid >> 5);
    int lane = tid & 31;
    int b = w >> 12, m = w & (Nc - 1);

    float acc0 = 0.f, acc1 = 0.f;
    for (int t = 0; t < Tc; t++) {
        float ys = 0.f, yx = 0.f;
#pragma unroll
        for (int s = 0; s < KSPLIT; s++) {
            const float* yp = g_Y + ((size_t)(s * Tc + t) * Nc + m) * NCP;
            ys += yp[b * Hc + lane];
            yx += yp[128 + b];
        }
        acc0 += yx * W1s[lane] + b1s[lane];
        acc1 += yx * W1s[lane + 32] + b1s[lane + 32];
#pragma unroll
        for (int j = 0; j < 32; j++) {
            float yj = __shfl_sync(0xffffffffu, ys, j);
            acc0 += yj * W1s[(j + 1) * 64 + lane];
            acc1 += yj * W1s[(j + 1) * 64 + lane + 32];
        }
        if (m < Nc / 2) {
            float r0 = sigmoidf_(acc0);
            float r1 = sigmoidf_(acc1);
            int n0 = 2 * m;
            size_t hidx = ((size_t)t * Bc + b) * NHc + (size_t)n0 * Hc + lane;
            size_t ridx = (((size_t)t * Bc + b) * Nc + n0) * Hc + lane;
            g_RH[ridx] = r0 * states[hidx];
            g_RH[ridx + Hc] = r1 * states[hidx + Hc];
        }
    }
    size_t o = ((size_t)b * Nc + m) * 64;
    g_g1fin[o + lane] = acc0;
    g_g1fin[o + 32 + lane] = acc1;
}

__global__ void final_kernel(const float* __restrict__ W2, const float* __restrict__ b2,
                             const float* __restrict__ states, float* __restrict__ out) {
    __shared__ float W2s[33 * 32];
    __shared__ float b2s[32];
    int tid = threadIdx.x;
    for (int i = tid; i < 33 * 32; i += 256) W2s[i] = W2[i];
    if (tid < 32) b2s[tid] = b2[tid];
    __syncthreads();

    int w = blockIdx.x * 8 + (tid >> 5);
    int lane = tid & 31;
    int b = w >> 12, n = w & (Nc - 1);

    float ys = 0.f, yx = 0.f;
    for (int t = 0; t < Tc; t++) {
#pragma unroll
        for (int s = 0; s < KSPLIT; s++) {
            const float* yp = g_Y + ((size_t)(s * Tc + t) * Nc + n) * NCP;
            ys += yp[b * Hc + lane];
            yx += yp[128 + b];
        }
    }
    float acc = yx * W2s[lane] + (float)Tc * b2s[lane];
#pragma unroll
    for (int j = 0; j < 32; j++) {
        float yj = __shfl_sync(0xffffffffu, ys, j);
        acc += yj * W2s[(j + 1) * 32 + lane];
    }
    float cc = tanhf(acc);
    float g1 = g_g1fin[((size_t)b * Nc + (Nc / 2) + (n >> 1)) * 64 + (n & 1) * 32 + lane];
    float u = sigmoidf_(g1);
    float h = states[((size_t)(Tc - 1) * Bc + b) * NHc + (size_t)n * Hc + lane];
    out[(size_t)b * NHc + (size_t)n * Hc + lane] = u * h + (1.f - u) * cc;
}

// ---------------------------------------------------------------------------
extern "C" void kernel_launch(void* const* d_in, const int* in_sizes, int n_in,
                              void* d_out, int out_size) {
    const float* inputs = (const float*)d_in[0];
    const float* states = (const float*)d_in[1];
    const float* dtw    = (const float*)d_in[2];
    const float* spec   = (const float*)d_in[3];
    const float* lap    = (const float*)d_in[4];
    const float* td     = (const float*)d_in[5];
    const float* W1     = (const float*)d_in[6];
    const float* b1     = (const float*)d_in[7];
    const float* W2     = (const float*)d_in[8];
    const float* b2     = (const float*)d_in[9];
    float* out = (float*)d_out;

    cudaFuncSetAttribute(gemm_kernel, cudaFuncAttributeMaxDynamicSharedMemorySize, SMEM_DYN);

    probe_kernel<<<1, 32>>>();   // keeps ncu -s window on gemm1
    prep_kernel<<<(int)((size_t)Nc * Nc / 8 / 256), 256>>>(dtw, spec, lap, td);
    buildC_kernel<<<dim3(NCHUNK, Tc), 256>>>(inputs, states, 0);
    gemm_kernel<<<dim3(NMB, Tc, KSPLIT), 256, SMEM_DYN>>>(0);
    gate_kernel<<<(Bc * Nc) / 8, 256>>>(W1, b1, states);
    buildC_kernel<<<dim3(NCHUNK, Tc), 256>>>(inputs, states, 1);
    gemm_kernel<<<dim3(NMB, Tc, KSPLIT), 256, SMEM_DYN>>>(1);
    final_kernel<<<(Bc * Nc) / 8, 256>>>(W2, b2, states, out);
}